// round 13
// baseline (speedup 1.0000x reference)
#include <cuda_runtime.h>
#include <cuda_bf16.h>

// ---------------------------------------------------------------------------
// Problem constants
// ---------------------------------------------------------------------------
#define TOTAL_BINS 28749
#define N_HEADS    22
#define ROWS       4096     // BATCH * 2 channels
#define BATCH      2048
#define IDIM       2200     // N_HEADS * 50 * 2
#define H1DIM      1000
#define H2DIM      50
#define ODIM       13

// LOC = cumsum of CHROM_BINS
__constant__ int c_loc[N_HEADS + 1] = {
    0, 2490, 4912, 6895, 8797, 10612, 12320, 13913, 15364, 16748, 18086,
    19437, 20770, 21914, 22984, 24004, 24907, 25740, 26544, 27130, 27774,
    28241, 28749
};

// ---------------------------------------------------------------------------
// Scratch (static __device__ arrays; allocation inside kernel_launch is banned)
// ---------------------------------------------------------------------------
__device__ float g_combined[BATCH * IDIM];   // 18 MB
__device__ float g_z[BATCH * IDIM];          // 18 MB
__device__ float g_h1[BATCH * H1DIM];        // 8.2 MB
__device__ float g_h2[BATCH * H2DIM];        // 0.4 MB

// ---------------------------------------------------------------------------
// Generic NT SGEMM:  C[m,n] = sum_k A[m,k] * B[n,k] + bias[n]  (opt. leaky)
// Block tile: (64*GM) x (64*GN), BK=8, 256 threads (16x16), per-thread tile
// (4*GM) x (4*GN) using the split-64 register layout so smem reads are
// conflict-free float4s.
// ---------------------------------------------------------------------------
template <int GM, int GN, bool LEAKY>
__global__ __launch_bounds__(256) void gemm_nt(
    const float* __restrict__ A, int lda,
    const float* __restrict__ B, int ldb,
    const float* __restrict__ bias,
    float* __restrict__ C, int ldc,
    int M, int N, int K)
{
    constexpr int BM = 64 * GM;
    constexpr int BN = 64 * GN;
    constexpr int BK = 8;

    __shared__ __align__(16) float As[BK][BM];
    __shared__ __align__(16) float Bs[BK][BN];

    const int tid = threadIdx.x;
    const int tx  = tid & 15;
    const int ty  = tid >> 4;
    const int m0  = blockIdx.x * BM;
    const int n0  = blockIdx.y * BN;

    float acc[GM * 4][GN * 4];
#pragma unroll
    for (int i = 0; i < GM * 4; i++)
#pragma unroll
        for (int j = 0; j < GN * 4; j++)
            acc[i][j] = 0.f;

    for (int k0 = 0; k0 < K; k0 += BK) {
        // Load A tile -> As[k][m] (transposed, k-major rows for float4 reads)
#pragma unroll
        for (int idx = tid; idx < BM * BK; idx += 256) {
            int m  = idx >> 3;
            int k  = idx & 7;
            int gm = m0 + m;
            int gk = k0 + k;
            As[k][m] = (gm < M && gk < K) ? A[(size_t)gm * lda + gk] : 0.f;
        }
        // Load B tile -> Bs[k][n]
#pragma unroll
        for (int idx = tid; idx < BN * BK; idx += 256) {
            int n  = idx >> 3;
            int k  = idx & 7;
            int gn = n0 + n;
            int gk = k0 + k;
            Bs[k][n] = (gn < N && gk < K) ? B[(size_t)gn * ldb + gk] : 0.f;
        }
        __syncthreads();

#pragma unroll
        for (int kc = 0; kc < BK; kc++) {
            float av[GM * 4], bv[GN * 4];
#pragma unroll
            for (int g = 0; g < GM; g++) {
                float4 v = *reinterpret_cast<const float4*>(&As[kc][g * 64 + ty * 4]);
                av[g * 4 + 0] = v.x; av[g * 4 + 1] = v.y;
                av[g * 4 + 2] = v.z; av[g * 4 + 3] = v.w;
            }
#pragma unroll
            for (int g = 0; g < GN; g++) {
                float4 v = *reinterpret_cast<const float4*>(&Bs[kc][g * 64 + tx * 4]);
                bv[g * 4 + 0] = v.x; bv[g * 4 + 1] = v.y;
                bv[g * 4 + 2] = v.z; bv[g * 4 + 3] = v.w;
            }
#pragma unroll
            for (int i = 0; i < GM * 4; i++)
#pragma unroll
                for (int j = 0; j < GN * 4; j++)
                    acc[i][j] = fmaf(av[i], bv[j], acc[i][j]);
        }
        __syncthreads();
    }

    // Epilogue
#pragma unroll
    for (int i = 0; i < GM * 4; i++) {
        int m = m0 + (i >> 2) * 64 + ty * 4 + (i & 3);
        if (m >= M) continue;
#pragma unroll
        for (int j = 0; j < GN * 4; j++) {
            int n = n0 + (j >> 2) * 64 + tx * 4 + (j & 3);
            if (n < N) {
                float v = acc[i][j] + bias[n];
                if (LEAKY) v = (v > 0.f) ? v : 0.01f * v;
                C[(size_t)m * ldc + n] = v;
            }
        }
    }
}

// ---------------------------------------------------------------------------
// Heads stage: per-head segmented GEMM with scatter into `combined`.
// Block tile 128 x 64 (N=50 padded), grid = (4096/128, 22 heads).
// combined[b, head*100 + c*50 + o] = dot(input[r, a:a+K], head_w[o, a:a+K])
//                                    + head_b[head, o],  r = b*2 + c.
// ---------------------------------------------------------------------------
__global__ __launch_bounds__(256) void heads_kernel(
    const float* __restrict__ input,    // (4096, TOTAL_BINS) row-major
    const float* __restrict__ head_w,   // (50, TOTAL_BINS)
    const float* __restrict__ head_b,   // (22, 50)
    float* __restrict__ combined)       // (2048, 2200)
{
    constexpr int BM = 128;
    constexpr int BN = 64;
    constexpr int BK = 8;

    __shared__ __align__(16) float As[BK][BM];
    __shared__ __align__(16) float Bs[BK][BN];

    const int tid  = threadIdx.x;
    const int tx   = tid & 15;
    const int ty   = tid >> 4;
    const int head = blockIdx.y;
    const int a    = c_loc[head];
    const int K    = c_loc[head + 1] - a;
    const int m0   = blockIdx.x * BM;

    const float* A = input  + a;   // lda = TOTAL_BINS
    const float* B = head_w + a;   // ldb = TOTAL_BINS

    float acc[8][4];
#pragma unroll
    for (int i = 0; i < 8; i++)
#pragma unroll
        for (int j = 0; j < 4; j++)
            acc[i][j] = 0.f;

    for (int k0 = 0; k0 < K; k0 += BK) {
#pragma unroll
        for (int idx = tid; idx < BM * BK; idx += 256) {
            int m  = idx >> 3;
            int k  = idx & 7;
            int gk = k0 + k;
            As[k][m] = (gk < K) ? A[(size_t)(m0 + m) * TOTAL_BINS + gk] : 0.f;
        }
#pragma unroll
        for (int idx = tid; idx < BN * BK; idx += 256) {
            int n  = idx >> 3;
            int k  = idx & 7;
            int gk = k0 + k;
            Bs[k][n] = (n < 50 && gk < K) ? B[(size_t)n * TOTAL_BINS + gk] : 0.f;
        }
        __syncthreads();

#pragma unroll
        for (int kc = 0; kc < BK; kc++) {
            float av[8], bv[4];
            float4 v0 = *reinterpret_cast<const float4*>(&As[kc][ty * 4]);
            float4 v1 = *reinterpret_cast<const float4*>(&As[kc][64 + ty * 4]);
            av[0] = v0.x; av[1] = v0.y; av[2] = v0.z; av[3] = v0.w;
            av[4] = v1.x; av[5] = v1.y; av[6] = v1.z; av[7] = v1.w;
            float4 w = *reinterpret_cast<const float4*>(&Bs[kc][tx * 4]);
            bv[0] = w.x; bv[1] = w.y; bv[2] = w.z; bv[3] = w.w;
#pragma unroll
            for (int i = 0; i < 8; i++)
#pragma unroll
                for (int j = 0; j < 4; j++)
                    acc[i][j] = fmaf(av[i], bv[j], acc[i][j]);
        }
        __syncthreads();
    }

    // Scatter epilogue
#pragma unroll
    for (int i = 0; i < 8; i++) {
        int r  = m0 + (i >> 2) * 64 + ty * 4 + (i & 3);
        int bb = r >> 1;
        int cc = r & 1;
        size_t base = (size_t)bb * IDIM + head * 100 + cc * 50;
#pragma unroll
        for (int j = 0; j < 4; j++) {
            int n = tx * 4 + j;
            if (n < 50)
                combined[base + n] = acc[i][j] + head_b[head * 50 + n];
        }
    }
}

// ---------------------------------------------------------------------------
// Final tiny layer: out[b,o] = dot(h2[b,:], w3[o,:]) + b3[o]
// ---------------------------------------------------------------------------
__global__ void out_kernel(
    const float* __restrict__ h2,   // (2048, 50)
    const float* __restrict__ w3,   // (13, 50)
    const float* __restrict__ b3,   // (13,)
    float* __restrict__ out)        // (2048, 13)
{
    int idx = blockIdx.x * blockDim.x + threadIdx.x;
    if (idx >= BATCH * ODIM) return;
    int b = idx / ODIM;
    int o = idx - b * ODIM;
    float s = b3[o];
#pragma unroll
    for (int k = 0; k < H2DIM; k++)
        s = fmaf(h2[b * H2DIM + k], w3[o * H2DIM + k], s);
    out[idx] = s;
}

// ---------------------------------------------------------------------------
// Launch
// ---------------------------------------------------------------------------
extern "C" void kernel_launch(void* const* d_in, const int* in_sizes, int n_in,
                              void* d_out, int out_size)
{
    const float* input  = (const float*)d_in[0];   // (2048, 2, 28749)
    const float* head_w = (const float*)d_in[1];   // (50, 28749)
    const float* head_b = (const float*)d_in[2];   // (22, 50)
    const float* conc_w = (const float*)d_in[3];   // (2200, 2200)
    const float* conc_b = (const float*)d_in[4];   // (2200,)
    const float* w1     = (const float*)d_in[5];   // (1000, 2200)
    const float* b1     = (const float*)d_in[6];   // (1000,)
    const float* w2     = (const float*)d_in[7];   // (50, 1000)
    const float* b2     = (const float*)d_in[8];   // (50,)
    const float* w3     = (const float*)d_in[9];   // (13, 50)
    const float* b3     = (const float*)d_in[10];  // (13,)
    float* out = (float*)d_out;

    float *combined, *z, *h1, *h2;
    cudaGetSymbolAddress((void**)&combined, g_combined);
    cudaGetSymbolAddress((void**)&z,        g_z);
    cudaGetSymbolAddress((void**)&h1,       g_h1);
    cudaGetSymbolAddress((void**)&h2,       g_h2);

    // Stage 1: heads -> combined (2048 x 2200)
    heads_kernel<<<dim3(ROWS / 128, N_HEADS), 256>>>(input, head_w, head_b, combined);

    // Stage 2: z = combined @ conc_w^T + conc_b   (2048 x 2200, K=2200)
    gemm_nt<2, 2, false><<<dim3(BATCH / 128, (IDIM + 127) / 128), 256>>>(
        combined, IDIM, conc_w, IDIM, conc_b, z, IDIM, BATCH, IDIM, IDIM);

    // Stage 3: h1 = leaky(z @ w1^T + b1)          (2048 x 1000, K=2200)
    gemm_nt<2, 2, true><<<dim3(BATCH / 128, (H1DIM + 127) / 128), 256>>>(
        z, IDIM, w1, IDIM, b1, h1, H1DIM, BATCH, H1DIM, IDIM);

    // Stage 4: h2 = leaky(h1 @ w2^T + b2)         (2048 x 50, K=1000)
    gemm_nt<1, 1, true><<<dim3(BATCH / 64, 1), 256>>>(
        h1, H1DIM, w2, H1DIM, b2, h2, H2DIM, BATCH, H2DIM, H1DIM);

    // Stage 5: out = h2 @ w3^T + b3               (2048 x 13, K=50)
    out_kernel<<<(BATCH * ODIM + 255) / 256, 256>>>(h2, w3, b3, out);
}

// round 14
// speedup vs baseline: 1.0014x; 1.0014x over previous
#include <cuda_runtime.h>
#include <cuda_bf16.h>

// ---------------------------------------------------------------------------
// Problem constants
// ---------------------------------------------------------------------------
#define TOTAL_BINS 28749
#define N_HEADS    22
#define ROWS       4096     // BATCH * 2 channels
#define BATCH      2048
#define IDIM       2200     // N_HEADS * 50 * 2
#define H1DIM      1000
#define H2DIM      50
#define ODIM       13

// LOC = cumsum of CHROM_BINS
__constant__ int c_loc[N_HEADS + 1] = {
    0, 2490, 4912, 6895, 8797, 10612, 12320, 13913, 15364, 16748, 18086,
    19437, 20770, 21914, 22984, 24004, 24907, 25740, 26544, 27130, 27774,
    28241, 28749
};

// ---------------------------------------------------------------------------
// Scratch (static __device__ arrays; allocation inside kernel_launch is banned)
// ---------------------------------------------------------------------------
__device__ float g_combined[BATCH * IDIM];   // 18 MB
__device__ float g_z[BATCH * IDIM];          // 18 MB
__device__ float g_h1[BATCH * H1DIM];        // 8.2 MB
__device__ float g_h2[BATCH * H2DIM];        // 0.4 MB

// ---------------------------------------------------------------------------
// Generic NT SGEMM:  C[m,n] = sum_k A[m,k] * B[n,k] + bias[n]  (opt. leaky)
// Block tile: (64*GM) x (64*GN), BK=8, 256 threads (16x16), per-thread tile
// (4*GM) x (4*GN) using the split-64 register layout so smem reads are
// conflict-free float4s.
// ---------------------------------------------------------------------------
template <int GM, int GN, bool LEAKY>
__global__ __launch_bounds__(256) void gemm_nt(
    const float* __restrict__ A, int lda,
    const float* __restrict__ B, int ldb,
    const float* __restrict__ bias,
    float* __restrict__ C, int ldc,
    int M, int N, int K)
{
    constexpr int BM = 64 * GM;
    constexpr int BN = 64 * GN;
    constexpr int BK = 8;

    __shared__ __align__(16) float As[BK][BM];
    __shared__ __align__(16) float Bs[BK][BN];

    const int tid = threadIdx.x;
    const int tx  = tid & 15;
    const int ty  = tid >> 4;
    const int m0  = blockIdx.x * BM;
    const int n0  = blockIdx.y * BN;

    float acc[GM * 4][GN * 4];
#pragma unroll
    for (int i = 0; i < GM * 4; i++)
#pragma unroll
        for (int j = 0; j < GN * 4; j++)
            acc[i][j] = 0.f;

    for (int k0 = 0; k0 < K; k0 += BK) {
        // Load A tile -> As[k][m] (transposed, k-major rows for float4 reads)
#pragma unroll
        for (int idx = tid; idx < BM * BK; idx += 256) {
            int m  = idx >> 3;
            int k  = idx & 7;
            int gm = m0 + m;
            int gk = k0 + k;
            As[k][m] = (gm < M && gk < K) ? A[(size_t)gm * lda + gk] : 0.f;
        }
        // Load B tile -> Bs[k][n]
#pragma unroll
        for (int idx = tid; idx < BN * BK; idx += 256) {
            int n  = idx >> 3;
            int k  = idx & 7;
            int gn = n0 + n;
            int gk = k0 + k;
            Bs[k][n] = (gn < N && gk < K) ? B[(size_t)gn * ldb + gk] : 0.f;
        }
        __syncthreads();

#pragma unroll
        for (int kc = 0; kc < BK; kc++) {
            float av[GM * 4], bv[GN * 4];
#pragma unroll
            for (int g = 0; g < GM; g++) {
                float4 v = *reinterpret_cast<const float4*>(&As[kc][g * 64 + ty * 4]);
                av[g * 4 + 0] = v.x; av[g * 4 + 1] = v.y;
                av[g * 4 + 2] = v.z; av[g * 4 + 3] = v.w;
            }
#pragma unroll
            for (int g = 0; g < GN; g++) {
                float4 v = *reinterpret_cast<const float4*>(&Bs[kc][g * 64 + tx * 4]);
                bv[g * 4 + 0] = v.x; bv[g * 4 + 1] = v.y;
                bv[g * 4 + 2] = v.z; bv[g * 4 + 3] = v.w;
            }
#pragma unroll
            for (int i = 0; i < GM * 4; i++)
#pragma unroll
                for (int j = 0; j < GN * 4; j++)
                    acc[i][j] = fmaf(av[i], bv[j], acc[i][j]);
        }
        __syncthreads();
    }

    // Epilogue
#pragma unroll
    for (int i = 0; i < GM * 4; i++) {
        int m = m0 + (i >> 2) * 64 + ty * 4 + (i & 3);
        if (m >= M) continue;
#pragma unroll
        for (int j = 0; j < GN * 4; j++) {
            int n = n0 + (j >> 2) * 64 + tx * 4 + (j & 3);
            if (n < N) {
                float v = acc[i][j] + bias[n];
                if (LEAKY) v = (v > 0.f) ? v : 0.01f * v;
                C[(size_t)m * ldc + n] = v;
            }
        }
    }
}

// ---------------------------------------------------------------------------
// Heads stage: per-head segmented GEMM with scatter into `combined`.
// Block tile 128 x 64 (N=50 padded), grid = (4096/128, 22 heads).
// combined[b, head*100 + c*50 + o] = dot(input[r, a:a+K], head_w[o, a:a+K])
//                                    + head_b[head, o],  r = b*2 + c.
// ---------------------------------------------------------------------------
__global__ __launch_bounds__(256) void heads_kernel(
    const float* __restrict__ input,    // (4096, TOTAL_BINS) row-major
    const float* __restrict__ head_w,   // (50, TOTAL_BINS)
    const float* __restrict__ head_b,   // (22, 50)
    float* __restrict__ combined)       // (2048, 2200)
{
    constexpr int BM = 128;
    constexpr int BN = 64;
    constexpr int BK = 8;

    __shared__ __align__(16) float As[BK][BM];
    __shared__ __align__(16) float Bs[BK][BN];

    const int tid  = threadIdx.x;
    const int tx   = tid & 15;
    const int ty   = tid >> 4;
    const int head = blockIdx.y;
    const int a    = c_loc[head];
    const int K    = c_loc[head + 1] - a;
    const int m0   = blockIdx.x * BM;

    const float* A = input  + a;   // lda = TOTAL_BINS
    const float* B = head_w + a;   // ldb = TOTAL_BINS

    float acc[8][4];
#pragma unroll
    for (int i = 0; i < 8; i++)
#pragma unroll
        for (int j = 0; j < 4; j++)
            acc[i][j] = 0.f;

    for (int k0 = 0; k0 < K; k0 += BK) {
#pragma unroll
        for (int idx = tid; idx < BM * BK; idx += 256) {
            int m  = idx >> 3;
            int k  = idx & 7;
            int gk = k0 + k;
            As[k][m] = (gk < K) ? A[(size_t)(m0 + m) * TOTAL_BINS + gk] : 0.f;
        }
#pragma unroll
        for (int idx = tid; idx < BN * BK; idx += 256) {
            int n  = idx >> 3;
            int k  = idx & 7;
            int gk = k0 + k;
            Bs[k][n] = (n < 50 && gk < K) ? B[(size_t)n * TOTAL_BINS + gk] : 0.f;
        }
        __syncthreads();

#pragma unroll
        for (int kc = 0; kc < BK; kc++) {
            float av[8], bv[4];
            float4 v0 = *reinterpret_cast<const float4*>(&As[kc][ty * 4]);
            float4 v1 = *reinterpret_cast<const float4*>(&As[kc][64 + ty * 4]);
            av[0] = v0.x; av[1] = v0.y; av[2] = v0.z; av[3] = v0.w;
            av[4] = v1.x; av[5] = v1.y; av[6] = v1.z; av[7] = v1.w;
            float4 w = *reinterpret_cast<const float4*>(&Bs[kc][tx * 4]);
            bv[0] = w.x; bv[1] = w.y; bv[2] = w.z; bv[3] = w.w;
#pragma unroll
            for (int i = 0; i < 8; i++)
#pragma unroll
                for (int j = 0; j < 4; j++)
                    acc[i][j] = fmaf(av[i], bv[j], acc[i][j]);
        }
        __syncthreads();
    }

    // Scatter epilogue
#pragma unroll
    for (int i = 0; i < 8; i++) {
        int r  = m0 + (i >> 2) * 64 + ty * 4 + (i & 3);
        int bb = r >> 1;
        int cc = r & 1;
        size_t base = (size_t)bb * IDIM + head * 100 + cc * 50;
#pragma unroll
        for (int j = 0; j < 4; j++) {
            int n = tx * 4 + j;
            if (n < 50)
                combined[base + n] = acc[i][j] + head_b[head * 50 + n];
        }
    }
}

// ---------------------------------------------------------------------------
// Final tiny layer: out[b,o] = dot(h2[b,:], w3[o,:]) + b3[o]
// ---------------------------------------------------------------------------
__global__ void out_kernel(
    const float* __restrict__ h2,   // (2048, 50)
    const float* __restrict__ w3,   // (13, 50)
    const float* __restrict__ b3,   // (13,)
    float* __restrict__ out)        // (2048, 13)
{
    int idx = blockIdx.x * blockDim.x + threadIdx.x;
    if (idx >= BATCH * ODIM) return;
    int b = idx / ODIM;
    int o = idx - b * ODIM;
    float s = b3[o];
#pragma unroll
    for (int k = 0; k < H2DIM; k++)
        s = fmaf(h2[b * H2DIM + k], w3[o * H2DIM + k], s);
    out[idx] = s;
}

// ---------------------------------------------------------------------------
// Launch
// ---------------------------------------------------------------------------
extern "C" void kernel_launch(void* const* d_in, const int* in_sizes, int n_in,
                              void* d_out, int out_size)
{
    const float* input  = (const float*)d_in[0];   // (2048, 2, 28749)
    const float* head_w = (const float*)d_in[1];   // (50, 28749)
    const float* head_b = (const float*)d_in[2];   // (22, 50)
    const float* conc_w = (const float*)d_in[3];   // (2200, 2200)
    const float* conc_b = (const float*)d_in[4];   // (2200,)
    const float* w1     = (const float*)d_in[5];   // (1000, 2200)
    const float* b1     = (const float*)d_in[6];   // (1000,)
    const float* w2     = (const float*)d_in[7];   // (50, 1000)
    const float* b2     = (const float*)d_in[8];   // (50,)
    const float* w3     = (const float*)d_in[9];   // (13, 50)
    const float* b3     = (const float*)d_in[10];  // (13,)
    float* out = (float*)d_out;

    float *combined, *z, *h1, *h2;
    cudaGetSymbolAddress((void**)&combined, g_combined);
    cudaGetSymbolAddress((void**)&z,        g_z);
    cudaGetSymbolAddress((void**)&h1,       g_h1);
    cudaGetSymbolAddress((void**)&h2,       g_h2);

    // Stage 1: heads -> combined (2048 x 2200)
    heads_kernel<<<dim3(ROWS / 128, N_HEADS), 256>>>(input, head_w, head_b, combined);

    // Stage 2: z = combined @ conc_w^T + conc_b   (2048 x 2200, K=2200)
    gemm_nt<2, 2, false><<<dim3(BATCH / 128, (IDIM + 127) / 128), 256>>>(
        combined, IDIM, conc_w, IDIM, conc_b, z, IDIM, BATCH, IDIM, IDIM);

    // Stage 3: h1 = leaky(z @ w1^T + b1)          (2048 x 1000, K=2200)
    gemm_nt<2, 2, true><<<dim3(BATCH / 128, (H1DIM + 127) / 128), 256>>>(
        z, IDIM, w1, IDIM, b1, h1, H1DIM, BATCH, H1DIM, IDIM);

    // Stage 4: h2 = leaky(h1 @ w2^T + b2)         (2048 x 50, K=1000)
    gemm_nt<1, 1, true><<<dim3(BATCH / 64, 1), 256>>>(
        h1, H1DIM, w2, H1DIM, b2, h2, H2DIM, BATCH, H2DIM, H1DIM);

    // Stage 5: out = h2 @ w3^T + b3               (2048 x 13, K=50)
    out_kernel<<<(BATCH * ODIM + 255) / 256, 256>>>(h2, w3, b3, out);
}